// round 1
// baseline (speedup 1.0000x reference)
#include <cuda_runtime.h>
#include <cuda_bf16.h>

#define KBINS 16

// Per-element LCQ quantize-dequantize after constant hoisting:
//   middle (|x| < alpha):  bi = min(floor(16 * |x|/alpha), 15)
//                          y  = gamma[bi]*(xt - dst[bi]) + beta[bi]
//                          q  = rint(y * Qp)  in [0, Qp]
//                          z  = copysign(alpha * LUT[q], x)
//   high   (|x| >= alpha): z  = copysign(alpha, x)
// LUT[q] folds the second searchsorted + inverse affine (y_q takes only
// the 16 values q/15, since y in [0,1] for middle elements).

__device__ __forceinline__ float lcq_one(float xx, float alpha, float s,
                                         const float* __restrict__ sg,
                                         const float* __restrict__ sb,
                                         const float* __restrict__ sd,
                                         const float* __restrict__ lut) {
    float ax = fabsf(xx);
    if (ax < alpha) {
        float xt = ax / alpha;
        float t16 = xt * 16.0f;            // exact: multiply by power of 2
        int bi = (int)t16;
        bi = bi > 15 ? 15 : bi;
        float y = fmaf(sg[bi], xt - sd[bi], sb[bi]);
        int q = (int)rintf(y * s);          // rint == round-half-even == jnp.round
        q = q < 0 ? 0 : (q > 15 ? 15 : q);
        return copysignf(alpha * lut[q], xx);
    } else {
        return copysignf(alpha, xx);
    }
}

__global__ void lcq_kernel(const float* __restrict__ x,
                           const float* __restrict__ thr,
                           const float* __restrict__ theta,
                           const float* __restrict__ dst,
                           const int* __restrict__ qp,
                           float* __restrict__ out,
                           long long n) {
    __shared__ float s_gamma[KBINS];
    __shared__ float s_beta[KBINS];
    __shared__ float s_dst[KBINS];
    __shared__ float s_lut[KBINS];
    __shared__ float s_alpha;
    __shared__ float s_scale;

    if (threadIdx.x == 0) {
        // softmax(theta) with max-subtraction (matches jax.nn.softmax)
        float th[KBINS];
        float m = theta[0];
        #pragma unroll
        for (int i = 0; i < KBINS; i++) { th[i] = theta[i]; m = fmaxf(m, th[i]); }
        float sum = 0.0f;
        #pragma unroll
        for (int i = 0; i < KBINS; i++) { th[i] = expf(th[i] - m); sum += th[i]; }
        float inv = 1.0f / sum;
        float c = 0.0f;
        #pragma unroll
        for (int i = 0; i < KBINS; i++) {
            float t = th[i] * inv;
            s_gamma[i] = t * (float)KBINS;  // theta_tmp / delta, delta = 1/K
            s_beta[i]  = c;                 // [0, cumsum[:K-1]]
            s_dst[i]   = dst[i];
            c += t;
        }
        float s = (float)qp[0];             // Qp = 15
        // Expand LUT: for each quant level q, z_mid = (q/s - beta[i])/gamma[i] + dst[i]
        // where i = searchsorted(beta, q/s, 'right') - 1 = last j with beta[j] <= t.
        #pragma unroll
        for (int q = 0; q < KBINS; q++) {
            float t = (float)q / s;
            int idx = 0;
            #pragma unroll
            for (int j = 0; j < KBINS; j++)
                if (s_beta[j] <= t) idx = j;
            s_lut[q] = (t - s_beta[idx]) / s_gamma[idx] + s_dst[idx];
        }
        s_alpha = thr[0];
        s_scale = s;
    }
    __syncthreads();

    const float alpha = s_alpha;
    const float s = s_scale;

    long long gid = (long long)blockIdx.x * blockDim.x + threadIdx.x;
    long long stride = (long long)gridDim.x * blockDim.x;
    long long n4 = n >> 2;

    const float4* __restrict__ x4 = (const float4*)x;
    float4* __restrict__ o4 = (float4*)out;

    for (long long i = gid; i < n4; i += stride) {
        float4 v = x4[i];
        float4 r;
        r.x = lcq_one(v.x, alpha, s, s_gamma, s_beta, s_dst, s_lut);
        r.y = lcq_one(v.y, alpha, s, s_gamma, s_beta, s_dst, s_lut);
        r.z = lcq_one(v.z, alpha, s, s_gamma, s_beta, s_dst, s_lut);
        r.w = lcq_one(v.w, alpha, s, s_gamma, s_beta, s_dst, s_lut);
        o4[i] = r;
    }
    // scalar tail (n not divisible by 4)
    for (long long i = (n4 << 2) + gid; i < n; i += stride) {
        out[i] = lcq_one(x[i], alpha, s, s_gamma, s_beta, s_dst, s_lut);
    }
}

extern "C" void kernel_launch(void* const* d_in, const int* in_sizes, int n_in,
                              void* d_out, int out_size) {
    // metadata order: x, threshold, theta, dst, Qn, Qp, num_elements
    const float* x     = (const float*)d_in[0];
    const float* thr   = (const float*)d_in[1];
    const float* theta = (const float*)d_in[2];
    const float* dst   = (const float*)d_in[3];
    const int*   qp    = (const int*)d_in[5];
    float* out = (float*)d_out;

    long long n = (long long)in_sizes[0];

    const int threads = 256;
    // ~16 CTAs per SM worth of grid-stride work; memory-bound, so modest grid
    // with grid-stride keeps per-block LUT setup overhead negligible.
    long long n4 = (n + 3) >> 2;
    int blocks = (int)((n4 + threads - 1) / threads);
    const int max_blocks = 148 * 16;
    if (blocks > max_blocks) blocks = max_blocks;
    if (blocks < 1) blocks = 1;

    lcq_kernel<<<blocks, threads>>>(x, thr, theta, dst, qp, out, n);
}

// round 2
// speedup vs baseline: 1.6846x; 1.6846x over previous
#include <cuda_runtime.h>
#include <cuda_bf16.h>

#define KBINS 16

// Branchless LCQ quantize-dequantize.
//
// Precompute (per block, thread 0):
//   theta_tmp = softmax(theta); gamma = theta_tmp*K; beta = [0, cumsum[:K-1]]
//   tab[i] = { s*gamma[i]/16 , s*beta[i] }        (float2, s = Qp)
//   lutA[q] = alpha * expand(q/s)                 (16-entry output LUT)
//   c = 16 / alpha
//
// Per element:
//   f    = min(|x| * c, 16)          // f in [0,16]; f=16 <=> high region
//   bi   = min((int)f, 15)
//   frac = f - (float)bi             // exact (Sterbenz)
//   y15  = tab[bi].x * frac + tab[bi].y    // = 15 * compress(|x|/alpha)
//   q    = rint(y15)                 // in [0,15]; q=15 at boundary/high
//   out  = copysign(lutA[q], x)      // lutA[15] = alpha*1 -> high case
//
// lutA folds the second searchsorted + inverse affine: for middle elements
// y in [0,1], so y_q takes only the 16 values q/15.

__global__ void __launch_bounds__(256)
lcq_kernel(const float* __restrict__ x,
           const float* __restrict__ thr,
           const float* __restrict__ theta,
           const float* __restrict__ dst,
           const int* __restrict__ qp,
           float* __restrict__ out,
           long long n) {
    __shared__ float2 s_tab[KBINS];    // {s*gamma/16, s*beta}
    __shared__ float  s_lutA[KBINS];   // alpha * expand(q/s)
    __shared__ float  s_c;             // 16/alpha

    if (threadIdx.x == 0) {
        float th[KBINS];
        float m = theta[0];
        #pragma unroll
        for (int i = 0; i < KBINS; i++) { th[i] = theta[i]; m = fmaxf(m, th[i]); }
        float sum = 0.0f;
        #pragma unroll
        for (int i = 0; i < KBINS; i++) { th[i] = expf(th[i] - m); sum += th[i]; }
        float inv = 1.0f / sum;

        float gamma[KBINS], beta[KBINS];
        float c = 0.0f;
        #pragma unroll
        for (int i = 0; i < KBINS; i++) {
            float t = th[i] * inv;
            gamma[i] = t * (float)KBINS;
            beta[i]  = c;
            c += t;
        }

        float s = (float)qp[0];        // Qp (=15)
        float alpha = thr[0];

        #pragma unroll
        for (int i = 0; i < KBINS; i++)
            s_tab[i] = make_float2(s * gamma[i] * 0.0625f, s * beta[i]);

        // expand LUT: idx = last j with beta[j] <= t
        #pragma unroll
        for (int q = 0; q < KBINS; q++) {
            float t = (float)q / s;
            int idx = 0;
            #pragma unroll
            for (int j = 0; j < KBINS; j++)
                if (beta[j] <= t) idx = j;
            s_lutA[q] = alpha * ((t - beta[idx]) / gamma[idx] + dst[idx]);
        }
        s_c = 16.0f / alpha;
    }
    __syncthreads();

    const float c = s_c;

    long long gid = (long long)blockIdx.x * blockDim.x + threadIdx.x;
    long long stride = (long long)gridDim.x * blockDim.x;
    long long n4 = n >> 2;

    const float4* __restrict__ x4 = (const float4*)x;
    float4* __restrict__ o4 = (float4*)out;

    for (long long i = gid; i < n4; i += stride) {
        float4 v = __ldcs(&x4[i]);
        float4 r;
        #pragma unroll
        for (int k = 0; k < 4; k++) {
            float xx = (&v.x)[k];
            float f = fminf(fabsf(xx) * c, 16.0f);
            int bi = (int)f;                    // trunc
            bi = bi > 15 ? 15 : bi;
            float frac = f - (float)bi;         // exact
            float2 gb = s_tab[bi];
            float y15 = fmaf(gb.x, frac, gb.y); // 15 * compress(xt)
            int q = (int)rintf(y15);            // round-half-even, in [0,15]
            q = q > 15 ? 15 : q;                // safety clamp
            float za = s_lutA[q];
            (&r.x)[k] = copysignf(za, xx);
        }
        __stcs(&o4[i], r);
    }
    // scalar tail
    for (long long i = (n4 << 2) + gid; i < n; i += stride) {
        float xx = x[i];
        float f = fminf(fabsf(xx) * c, 16.0f);
        int bi = (int)f;
        bi = bi > 15 ? 15 : bi;
        float frac = f - (float)bi;
        float2 gb = s_tab[bi];
        float y15 = fmaf(gb.x, frac, gb.y);
        int q = (int)rintf(y15);
        q = q > 15 ? 15 : q;
        out[i] = copysignf(s_lutA[q], xx);
    }
}

extern "C" void kernel_launch(void* const* d_in, const int* in_sizes, int n_in,
                              void* d_out, int out_size) {
    // metadata order: x, threshold, theta, dst, Qn, Qp, num_elements
    const float* x     = (const float*)d_in[0];
    const float* thr   = (const float*)d_in[1];
    const float* theta = (const float*)d_in[2];
    const float* dst   = (const float*)d_in[3];
    const int*   qp    = (const int*)d_in[5];
    float* out = (float*)d_out;

    long long n = (long long)in_sizes[0];

    const int threads = 256;
    long long n4 = (n + 3) >> 2;
    int blocks = (int)((n4 + threads - 1) / threads);
    const int max_blocks = 148 * 16;
    if (blocks > max_blocks) blocks = max_blocks;
    if (blocks < 1) blocks = 1;

    lcq_kernel<<<blocks, threads>>>(x, thr, theta, dst, qp, out, n);
}

// round 3
// speedup vs baseline: 1.7380x; 1.0317x over previous
#include <cuda_runtime.h>
#include <cuda_bf16.h>

#define KBINS 16
#define UNROLL 4

// Branchless LCQ quantize-dequantize, 4x-unrolled grid-stride for MLP.
//
// Per element:
//   f    = min(|x| * (16/alpha), 16)       // f in [0,16]; f=16 <=> high region
//   bi   = min((int)f, 15)
//   frac = f - (float)bi                   // exact (Sterbenz)
//   y15  = tab[bi].x * frac + tab[bi].y    // = Qp * compress(|x|/alpha)
//   q    = rint(y15)                       // round-half-even, in [0,15]
//   out  = copysign(lutA[q], x)            // lutA[15] = alpha  -> high case
//
// tab/lutA fold softmax, cumsum, both searchsorteds, the affine maps, the
// quantizer scale and the final alpha multiply into two 16-entry tables.

__device__ __forceinline__ float lcq_elem(float xx, float c,
                                          const float2* __restrict__ tab,
                                          const float* __restrict__ lutA) {
    float f = fminf(fabsf(xx) * c, 16.0f);
    int bi = (int)f;
    bi = bi > 15 ? 15 : bi;
    float frac = f - (float)bi;
    float2 gb = tab[bi];
    float y15 = fmaf(gb.x, frac, gb.y);
    int q = (int)rintf(y15);
    q = q > 15 ? 15 : q;
    return copysignf(lutA[q], xx);
}

__global__ void __launch_bounds__(256)
lcq_kernel(const float* __restrict__ x,
           const float* __restrict__ thr,
           const float* __restrict__ theta,
           const float* __restrict__ dst,
           const int* __restrict__ qp,
           float* __restrict__ out,
           long long n) {
    __shared__ float2 s_tab[KBINS];    // {s*gamma/16, s*beta}
    __shared__ float  s_lutA[KBINS];   // alpha * expand(q/s)
    __shared__ float  s_c;             // 16/alpha

    if (threadIdx.x == 0) {
        float th[KBINS];
        float m = theta[0];
        #pragma unroll
        for (int i = 0; i < KBINS; i++) { th[i] = theta[i]; m = fmaxf(m, th[i]); }
        float sum = 0.0f;
        #pragma unroll
        for (int i = 0; i < KBINS; i++) { th[i] = expf(th[i] - m); sum += th[i]; }
        float inv = 1.0f / sum;

        float gamma[KBINS], beta[KBINS];
        float c = 0.0f;
        #pragma unroll
        for (int i = 0; i < KBINS; i++) {
            float t = th[i] * inv;
            gamma[i] = t * (float)KBINS;
            beta[i]  = c;
            c += t;
        }

        float s = (float)qp[0];        // Qp (=15)
        float alpha = thr[0];

        #pragma unroll
        for (int i = 0; i < KBINS; i++)
            s_tab[i] = make_float2(s * gamma[i] * 0.0625f, s * beta[i]);

        // expand LUT: idx = last j with beta[j] <= t
        #pragma unroll
        for (int q = 0; q < KBINS; q++) {
            float t = (float)q / s;
            int idx = 0;
            #pragma unroll
            for (int j = 0; j < KBINS; j++)
                if (beta[j] <= t) idx = j;
            s_lutA[q] = alpha * ((t - beta[idx]) / gamma[idx] + dst[idx]);
        }
        s_c = 16.0f / alpha;
    }
    __syncthreads();

    const float c = s_c;

    long long gid = (long long)blockIdx.x * blockDim.x + threadIdx.x;
    long long stride = (long long)gridDim.x * blockDim.x;
    long long n4 = n >> 2;

    const float4* __restrict__ x4 = (const float4*)x;
    float4* __restrict__ o4 = (float4*)out;

    long long i = gid;
    // Main: 4 independent float4 loads in flight per iteration (MLP=4).
    for (; i + 3 * stride < n4; i += (long long)UNROLL * stride) {
        float4 v0 = __ldcs(&x4[i]);
        float4 v1 = __ldcs(&x4[i + stride]);
        float4 v2 = __ldcs(&x4[i + 2 * stride]);
        float4 v3 = __ldcs(&x4[i + 3 * stride]);

        float4 r0, r1, r2, r3;
        #pragma unroll
        for (int k = 0; k < 4; k++) {
            (&r0.x)[k] = lcq_elem((&v0.x)[k], c, s_tab, s_lutA);
            (&r1.x)[k] = lcq_elem((&v1.x)[k], c, s_tab, s_lutA);
            (&r2.x)[k] = lcq_elem((&v2.x)[k], c, s_tab, s_lutA);
            (&r3.x)[k] = lcq_elem((&v3.x)[k], c, s_tab, s_lutA);
        }
        __stcs(&o4[i], r0);
        __stcs(&o4[i + stride], r1);
        __stcs(&o4[i + 2 * stride], r2);
        __stcs(&o4[i + 3 * stride], r3);
    }
    // Remainder float4s
    for (; i < n4; i += stride) {
        float4 v = __ldcs(&x4[i]);
        float4 r;
        #pragma unroll
        for (int k = 0; k < 4; k++)
            (&r.x)[k] = lcq_elem((&v.x)[k], c, s_tab, s_lutA);
        __stcs(&o4[i], r);
    }
    // Scalar tail
    for (long long j = (n4 << 2) + gid; j < n; j += stride) {
        out[j] = lcq_elem(x[j], c, s_tab, s_lutA);
    }
}

extern "C" void kernel_launch(void* const* d_in, const int* in_sizes, int n_in,
                              void* d_out, int out_size) {
    // metadata order: x, threshold, theta, dst, Qn, Qp, num_elements
    const float* x     = (const float*)d_in[0];
    const float* thr   = (const float*)d_in[1];
    const float* theta = (const float*)d_in[2];
    const float* dst   = (const float*)d_in[3];
    const int*   qp    = (const int*)d_in[5];
    float* out = (float*)d_out;

    long long n = (long long)in_sizes[0];

    const int threads = 256;
    long long n4 = (n + 3) >> 2;
    int blocks = (int)((n4 + threads - 1) / threads);
    const int max_blocks = 148 * 16;   // grid-stride; ~2 waves at occ 8
    if (blocks > max_blocks) blocks = max_blocks;
    if (blocks < 1) blocks = 1;

    lcq_kernel<<<blocks, threads>>>(x, thr, theta, dst, qp, out, n);
}

// round 4
// speedup vs baseline: 1.9453x; 1.1193x over previous
#include <cuda_runtime.h>
#include <cuda_bf16.h>

#define KBINS 16

// Branchless LCQ quantize-dequantize, 4x front-batched loads, in-place compute.
//
// Per element (clamp-free):
//   f    = min(|x| * (16/alpha), 15.9999990)   // one ulp below 16
//   bi   = (int)f                              // <= 15 guaranteed
//   frac = f - (float)bi
//   y15  = tab[bi].x * frac + tab[bi].y        // = Qp * compress(|x|/alpha)
//   q    = rint(y15)                           // in [0,15], no clamp needed
//   out  = copysign(lutA[q], x)                // lutA[15] = alpha -> high region

__device__ __forceinline__ float lcq_elem(float xx, float c,
                                          const float2* __restrict__ tab,
                                          const float* __restrict__ lutA) {
    float f = fminf(fabsf(xx) * c, 15.9999990f);
    int bi = (int)f;                    // trunc, <= 15
    float frac = f - (float)bi;
    float2 gb = tab[bi];
    float y15 = fmaf(gb.x, frac, gb.y);
    int q = (int)rintf(y15);            // round-half-even, in [0,15]
    return copysignf(lutA[q], xx);
}

__device__ __forceinline__ void lcq_vec4(float4& v, float c,
                                         const float2* __restrict__ tab,
                                         const float* __restrict__ lutA) {
    v.x = lcq_elem(v.x, c, tab, lutA);
    v.y = lcq_elem(v.y, c, tab, lutA);
    v.z = lcq_elem(v.z, c, tab, lutA);
    v.w = lcq_elem(v.w, c, tab, lutA);
}

__global__ void __launch_bounds__(256, 5)
lcq_kernel(const float* __restrict__ x,
           const float* __restrict__ thr,
           const float* __restrict__ theta,
           const float* __restrict__ dst,
           const int* __restrict__ qp,
           float* __restrict__ out,
           long long n) {
    __shared__ float2 s_tab[KBINS];    // {s*gamma/16, s*beta}
    __shared__ float  s_lutA[KBINS];   // alpha * expand(q/s)
    __shared__ float  s_c;             // 16/alpha

    if (threadIdx.x == 0) {
        float th[KBINS];
        float m = theta[0];
        #pragma unroll
        for (int i = 0; i < KBINS; i++) { th[i] = theta[i]; m = fmaxf(m, th[i]); }
        float sum = 0.0f;
        #pragma unroll
        for (int i = 0; i < KBINS; i++) { th[i] = expf(th[i] - m); sum += th[i]; }
        float inv = 1.0f / sum;

        float gamma[KBINS], beta[KBINS];
        float c = 0.0f;
        #pragma unroll
        for (int i = 0; i < KBINS; i++) {
            float t = th[i] * inv;
            gamma[i] = t * (float)KBINS;
            beta[i]  = c;
            c += t;
        }

        float s = (float)qp[0];        // Qp (=15)
        float alpha = thr[0];

        #pragma unroll
        for (int i = 0; i < KBINS; i++)
            s_tab[i] = make_float2(s * gamma[i] * 0.0625f, s * beta[i]);

        // expand LUT: idx = last j with beta[j] <= t
        #pragma unroll
        for (int q = 0; q < KBINS; q++) {
            float t = (float)q / s;
            int idx = 0;
            #pragma unroll
            for (int j = 0; j < KBINS; j++)
                if (beta[j] <= t) idx = j;
            s_lutA[q] = alpha * ((t - beta[idx]) / gamma[idx] + dst[idx]);
        }
        s_c = 16.0f / alpha;
    }
    __syncthreads();

    const float c = s_c;

    long long gid = (long long)blockIdx.x * blockDim.x + threadIdx.x;
    long long stride = (long long)gridDim.x * blockDim.x;
    long long n4 = n >> 2;

    const float4* __restrict__ x4 = (const float4*)x;
    float4* __restrict__ o4 = (float4*)out;

    long long i = gid;
    // Main: 4 independent LDG.128 issued up front (MLP=4), then compute+store
    // each vector in place so only ~4 float4s stay live (low reg pressure).
    for (; i + 3 * stride < n4; i += 4 * stride) {
        float4 v0 = __ldcs(&x4[i]);
        float4 v1 = __ldcs(&x4[i + stride]);
        float4 v2 = __ldcs(&x4[i + 2 * stride]);
        float4 v3 = __ldcs(&x4[i + 3 * stride]);

        lcq_vec4(v0, c, s_tab, s_lutA);  __stcs(&o4[i], v0);
        lcq_vec4(v1, c, s_tab, s_lutA);  __stcs(&o4[i + stride], v1);
        lcq_vec4(v2, c, s_tab, s_lutA);  __stcs(&o4[i + 2 * stride], v2);
        lcq_vec4(v3, c, s_tab, s_lutA);  __stcs(&o4[i + 3 * stride], v3);
    }
    // Remainder float4s
    for (; i < n4; i += stride) {
        float4 v = __ldcs(&x4[i]);
        lcq_vec4(v, c, s_tab, s_lutA);
        __stcs(&o4[i], v);
    }
    // Scalar tail
    for (long long j = (n4 << 2) + gid; j < n; j += stride) {
        out[j] = lcq_elem(x[j], c, s_tab, s_lutA);
    }
}

extern "C" void kernel_launch(void* const* d_in, const int* in_sizes, int n_in,
                              void* d_out, int out_size) {
    // metadata order: x, threshold, theta, dst, Qn, Qp, num_elements
    const float* x     = (const float*)d_in[0];
    const float* thr   = (const float*)d_in[1];
    const float* theta = (const float*)d_in[2];
    const float* dst   = (const float*)d_in[3];
    const int*   qp    = (const int*)d_in[5];
    float* out = (float*)d_out;

    long long n = (long long)in_sizes[0];

    const int threads = 256;
    long long n4 = (n + 3) >> 2;
    int blocks = (int)((n4 + threads - 1) / threads);
    const int max_blocks = 148 * 10;   // ~2 waves at 5 CTAs/SM, grid-stride
    if (blocks > max_blocks) blocks = max_blocks;
    if (blocks < 1) blocks = 1;

    lcq_kernel<<<blocks, threads>>>(x, thr, theta, dst, qp, out, n);
}